// round 1
// baseline (speedup 1.0000x reference)
#include <cuda_runtime.h>
#include <math.h>

#define Bk 1024
#define Tk 200
#define Hk 128
#define BT (1024*200)

#define AS_STRIDE 132
#define WS_STRIDE 132
#define LN_STRIDE 130

// Scratch (static device globals: allocation-free at launch time)
__device__ float g_x[3ull * BT * Hk];   // xu, xr, xg projections  [3][B*T][128]
__device__ float g_s[BT];               // attention scores
__device__ float g_att[BT];             // softmax(att) over T

__device__ __forceinline__ float sigmoidf_(float x) {
    return 1.0f / (1.0f + expf(-x));
}

// ---------------------------------------------------------------------------
// Kernel A: fused projection GEMMs.
// Per block: 128 rows of (b,t). Computes
//   s[b,t]  = dot(targets@W_w^T + W_b, history)        (attention score)
//   xu/xr/xg[b,t,:] = history @ {xu,xr,xg}_w^T + bias  (written to scratch)
// 256 threads, 8x8 register micro-tiles, smem tiles stored k-major (transposed).
// ---------------------------------------------------------------------------
__global__ void proj_kernel(const float* __restrict__ targets,
                            const float* __restrict__ history,
                            const float* __restrict__ Ww,  const float* __restrict__ Wb,
                            const float* __restrict__ xuw, const float* __restrict__ xub,
                            const float* __restrict__ xrw, const float* __restrict__ xrb,
                            const float* __restrict__ xgw, const float* __restrict__ xgb)
{
    extern __shared__ float sm[];
    float* Ts  = sm;                     // [128 k][AS_STRIDE rows] targets, transposed
    float* Hs  = Ts + 128 * AS_STRIDE;   // history, transposed
    float* Ws  = Hs + 128 * AS_STRIDE;   // current weight, transposed [k][o]
    float* bsm = Ws + 128 * AS_STRIDE;   // [128] bias
    float* red = bsm + 128;              // [128][16] score reduction

    const int tid = threadIdx.x;
    const int bt0 = blockIdx.x * 128;

    // Stage input tiles (transposed: [k][row])
    for (int idx = tid; idx < 128 * 128; idx += 256) {
        int row = idx >> 7, k = idx & 127;
        Ts[k * AS_STRIDE + row] = targets[(size_t)(bt0 + row) * 128 + k];
        Hs[k * AS_STRIDE + row] = history[(size_t)(bt0 + row) * 128 + k];
    }

    const int tx = tid & 15, ty = tid >> 4;
    const int r0 = ty * 8, c0 = tx * 8;

    const float* wptr[4] = {Ww, xuw, xrw, xgw};
    const float* bptr[4] = {Wb, xub, xrb, xgb};

    for (int w = 0; w < 4; w++) {
        __syncthreads();   // tiles staged / previous Ws+red consumers done
        for (int idx = tid; idx < 128 * 128; idx += 256) {
            int o = idx >> 7, k = idx & 127;          // global W[o][k]
            Ws[k * AS_STRIDE + o] = wptr[w][idx];
        }
        if (tid < 128) bsm[tid] = bptr[w][tid];
        __syncthreads();

        const float* A_s = (w == 0) ? Ts : Hs;

        float acc[8][8];
        #pragma unroll
        for (int i = 0; i < 8; i++)
            #pragma unroll
            for (int j = 0; j < 8; j++) acc[i][j] = 0.0f;

        #pragma unroll 4
        for (int k = 0; k < 128; k++) {
            const float* Ak = A_s + k * AS_STRIDE;
            const float* Wk = Ws + k * AS_STRIDE;
            float4 a0 = *(const float4*)(Ak + r0);
            float4 a1 = *(const float4*)(Ak + r0 + 4);
            float4 w0 = *(const float4*)(Wk + c0);
            float4 w1 = *(const float4*)(Wk + c0 + 4);
            float av[8] = {a0.x, a0.y, a0.z, a0.w, a1.x, a1.y, a1.z, a1.w};
            float wv[8] = {w0.x, w0.y, w0.z, w0.w, w1.x, w1.y, w1.z, w1.w};
            #pragma unroll
            for (int i = 0; i < 8; i++)
                #pragma unroll
                for (int j = 0; j < 8; j++)
                    acc[i][j] += av[i] * wv[j];
        }

        if (w == 0) {
            // score: per-row dot of (aw + bias) with history row
            #pragma unroll
            for (int i = 0; i < 8; i++) {
                float p = 0.0f;
                #pragma unroll
                for (int j = 0; j < 8; j++)
                    p += (acc[i][j] + bsm[c0 + j]) * Hs[(c0 + j) * AS_STRIDE + (r0 + i)];
                red[(r0 + i) * 16 + tx] = p;
            }
            __syncthreads();
            if (tid < 128) {
                float s = 0.0f;
                #pragma unroll
                for (int x = 0; x < 16; x++) s += red[tid * 16 + x];
                g_s[(size_t)bt0 + tid] = s;
            }
        } else {
            float* dst = g_x + (size_t)(w - 1) * BT * 128 + (size_t)bt0 * 128;
            #pragma unroll
            for (int i = 0; i < 8; i++) {
                float4 v0 = make_float4(acc[i][0] + bsm[c0 + 0], acc[i][1] + bsm[c0 + 1],
                                        acc[i][2] + bsm[c0 + 2], acc[i][3] + bsm[c0 + 3]);
                float4 v1 = make_float4(acc[i][4] + bsm[c0 + 4], acc[i][5] + bsm[c0 + 5],
                                        acc[i][6] + bsm[c0 + 6], acc[i][7] + bsm[c0 + 7]);
                *(float4*)&dst[(size_t)(r0 + i) * 128 + c0]     = v0;
                *(float4*)&dst[(size_t)(r0 + i) * 128 + c0 + 4] = v1;
            }
        }
    }
}

// ---------------------------------------------------------------------------
// Kernel B: softmax over T per batch row.
// ---------------------------------------------------------------------------
__global__ void softmax_kernel()
{
    __shared__ float red[256];
    const int b = blockIdx.x;
    const int tid = threadIdx.x;

    float v = (tid < Tk) ? g_s[(size_t)b * Tk + tid] : -1e30f;
    red[tid] = v;
    __syncthreads();
    for (int s = 128; s > 0; s >>= 1) {
        if (tid < s) red[tid] = fmaxf(red[tid], red[tid + s]);
        __syncthreads();
    }
    const float mx = red[0];
    __syncthreads();
    float e = (tid < Tk) ? expf(v - mx) : 0.0f;
    red[tid] = e;
    __syncthreads();
    for (int s = 128; s > 0; s >>= 1) {
        if (tid < s) red[tid] += red[tid + s];
        __syncthreads();
    }
    const float inv = 1.0f / red[0];
    if (tid < Tk) g_att[(size_t)b * Tk + tid] = e * inv;
}

// ---------------------------------------------------------------------------
// Kernel C: persistent GRU-style scan + final linear.
// 128 blocks x 8 batch rows, 384 threads. Thread tid -> (gate m = tid/128,
// output col oc = tid%128); holds 8-row accumulators. Weights resident in smem.
// ---------------------------------------------------------------------------
__global__ void scan_kernel(const float* __restrict__ targets,
                            const float* __restrict__ huw, const float* __restrict__ hub,
                            const float* __restrict__ hrw, const float* __restrict__ hrb,
                            const float* __restrict__ hgw, const float* __restrict__ hgb,
                            const float* __restrict__ ln2w, const float* __restrict__ ln2b,
                            float* __restrict__ out)
{
    extern __shared__ float sm[];
    float* W_s  = sm;                          // [3][128 o][WS_STRIDE k]
    float* bsm  = W_s + 3 * 128 * WS_STRIDE;   // [3][128]
    float* h_s  = bsm + 3 * 128;               // [8][128]
    float* r_s  = h_s + 8 * 128;               // [8][128] reset gate / targets stage
    float* gg_s = r_s + 8 * 128;               // [8][128] candidate g

    const int tid = threadIdx.x;
    const int b0 = blockIdx.x * 8;

    {
        const float* hw[3] = {huw, hrw, hgw};
        const float* hb[3] = {hub, hrb, hgb};
        for (int m = 0; m < 3; m++) {
            for (int idx = tid; idx < 128 * 128; idx += 384) {
                int o = idx >> 7, k = idx & 127;
                W_s[(m * 128 + o) * WS_STRIDE + k] = hw[m][idx];
            }
            if (tid < 128) bsm[m * 128 + tid] = hb[m][tid];
        }
    }
    for (int idx = tid; idx < 8 * 128; idx += 384) h_s[idx] = 0.0f;
    __syncthreads();

    const int m  = tid >> 7;     // 0: update u, 1: reset r, 2: candidate g
    const int oc = tid & 127;
    const float* wrow = &W_s[(m * 128 + oc) * WS_STRIDE];
    const float  bias = bsm[m * 128 + oc];
    const float* xbase = g_x + (size_t)m * BT * 128 + oc;

    for (int t = 0; t < Tk; t++) {
        // issue global loads early (latency hidden behind matvec)
        float xv[8], attv[8];
        #pragma unroll
        for (int i = 0; i < 8; i++)
            xv[i] = xbase[(size_t)((b0 + i) * Tk + t) * 128];
        if (m == 0) {
            #pragma unroll
            for (int i = 0; i < 8; i++) attv[i] = g_att[(size_t)(b0 + i) * Tk + t];
        }

        float acc[8];
        #pragma unroll
        for (int i = 0; i < 8; i++) acc[i] = 0.0f;

        #pragma unroll 4
        for (int k = 0; k < 128; k += 4) {
            float4 w4 = *(const float4*)&wrow[k];
            #pragma unroll
            for (int i = 0; i < 8; i++) {
                float4 h4 = *(const float4*)&h_s[i * 128 + k];
                acc[i] += h4.x * w4.x + h4.y * w4.y + h4.z * w4.z + h4.w * w4.w;
            }
        }

        float ureg[8];
        if (m == 0) {
            #pragma unroll
            for (int i = 0; i < 8; i++)
                ureg[i] = sigmoidf_(acc[i] + bias + xv[i]) * attv[i];
        } else if (m == 1) {
            #pragma unroll
            for (int i = 0; i < 8; i++)
                r_s[i * 128 + oc] = sigmoidf_(acc[i] + bias + xv[i]);
        } else {
            #pragma unroll
            for (int i = 0; i < 8; i++)
                acc[i] += bias;                       // z = h@hg^T + hg_b (no xg here!)
        }
        __syncthreads();                              // r_s ready; matvec reads of h done

        if (m == 2) {
            #pragma unroll
            for (int i = 0; i < 8; i++)
                gg_s[i * 128 + oc] = tanhf(xv[i] + r_s[i * 128 + oc] * acc[i]);
        }
        __syncthreads();                              // gg_s ready

        if (m == 0) {
            #pragma unroll
            for (int i = 0; i < 8; i++) {
                float h = h_s[i * 128 + oc];
                h_s[i * 128 + oc] = h + ureg[i] * (gg_s[i * 128 + oc] - h);
            }
        }
        __syncthreads();                              // h ready for next step
    }

    // ---- final: out = concat(h, targets[:,0]) @ ln2_w^T + ln2_b ----
    // stage targets[b,0,:] into r_s; ln2_w transposed into W_s region
    for (int idx = tid; idx < 8 * 128; idx += 384)
        r_s[idx] = targets[(size_t)((b0 + (idx >> 7)) * Tk) * 128 + (idx & 127)];
    float* lw = W_s;   // [256 k][LN_STRIDE] transposed
    for (int idx = tid; idx < 128 * 256; idx += 384) {
        int o = idx >> 8, k2 = idx & 255;             // ln2_w[o][k2]
        lw[k2 * LN_STRIDE + o] = ln2w[idx];
    }
    __syncthreads();

    if (tid < 128) {
        const int o = tid;
        float acc2[8];
        const float b2 = ln2b[o];
        #pragma unroll
        for (int i = 0; i < 8; i++) acc2[i] = b2;
        #pragma unroll 2
        for (int k = 0; k < 128; k++) {
            float wh = lw[k * LN_STRIDE + o];
            float wt = lw[(128 + k) * LN_STRIDE + o];
            #pragma unroll
            for (int i = 0; i < 8; i++)
                acc2[i] += h_s[i * 128 + k] * wh + r_s[i * 128 + k] * wt;
        }
        #pragma unroll
        for (int i = 0; i < 8; i++)
            out[(size_t)(b0 + i) * 128 + o] = acc2[i];
    }
}

// ---------------------------------------------------------------------------
extern "C" void kernel_launch(void* const* d_in, const int* in_sizes, int n_in,
                              void* d_out, int out_size)
{
    const float* targets = (const float*)d_in[0];
    const float* history = (const float*)d_in[1];
    const float* Ww  = (const float*)d_in[2];
    const float* Wb  = (const float*)d_in[3];
    const float* xuw = (const float*)d_in[4];
    const float* xub = (const float*)d_in[5];
    const float* huw = (const float*)d_in[6];
    const float* hub = (const float*)d_in[7];
    const float* xrw = (const float*)d_in[8];
    const float* xrb = (const float*)d_in[9];
    const float* hrw = (const float*)d_in[10];
    const float* hrb = (const float*)d_in[11];
    const float* xgw = (const float*)d_in[12];
    const float* xgb = (const float*)d_in[13];
    const float* hgw = (const float*)d_in[14];
    const float* hgb = (const float*)d_in[15];
    const float* ln2w = (const float*)d_in[16];
    const float* ln2b = (const float*)d_in[17];
    float* out = (float*)d_out;

    const size_t smA = (size_t)(3 * 128 * AS_STRIDE + 128 + 128 * 16) * sizeof(float);
    const size_t smC = (size_t)(3 * 128 * WS_STRIDE + 3 * 128 + 3 * 8 * 128) * sizeof(float);

    cudaFuncSetAttribute(proj_kernel, cudaFuncAttributeMaxDynamicSharedMemorySize, (int)smA);
    cudaFuncSetAttribute(scan_kernel, cudaFuncAttributeMaxDynamicSharedMemorySize, (int)smC);

    proj_kernel<<<BT / 128, 256, smA>>>(targets, history, Ww, Wb,
                                        xuw, xub, xrw, xrb, xgw, xgb);
    softmax_kernel<<<Bk, 256>>>();
    scan_kernel<<<Bk / 8, 384, smC>>>(targets, huw, hub, hrw, hrb, hgw, hgb,
                                      ln2w, ln2b, out);
}

// round 2
// speedup vs baseline: 1.0640x; 1.0640x over previous
#include <cuda_runtime.h>
#include <math.h>

#define Bk 1024
#define Tk 200
#define Hk 128
#define BT (1024*200)

#define PJ 132          // proj smem stride
#define WS_STRIDE 132
#define LN_STRIDE 130

// Scratch (static device globals: allocation-free at launch time)
__device__ float g_x[3ull * BT * Hk];   // xu, xr, xg projections  [3][B*T][128]
__device__ float g_s[BT];               // attention scores
__device__ float g_att[BT];             // softmax(att) over T

typedef unsigned long long u64;

__device__ __forceinline__ float sigmoidf_(float x) {
    return 1.0f / (1.0f + expf(-x));
}

// ---- packed f32x2 helpers (SASS FFMA2 path, PTX-only) ----
__device__ __forceinline__ u64 ffma2(u64 a, u64 b, u64 c) {
    u64 d;
    asm("fma.rn.f32x2 %0, %1, %2, %3;" : "=l"(d) : "l"(a), "l"(b), "l"(c));
    return d;
}
__device__ __forceinline__ u64 fadd2(u64 a, u64 b) {
    u64 d;
    asm("add.rn.f32x2 %0, %1, %2;" : "=l"(d) : "l"(a), "l"(b));
    return d;
}
__device__ __forceinline__ u64 dup2(float x) {
    u64 d;
    asm("mov.b64 %0, {%1, %1};" : "=l"(d) : "f"(x));
    return d;
}
__device__ __forceinline__ float2 unpack2(u64 v) {
    float2 r;
    asm("mov.b64 {%0, %1}, %2;" : "=f"(r.x), "=f"(r.y) : "l"(v));
    return r;
}

// ---------------------------------------------------------------------------
// Kernel A: projection GEMMs, one weight per blockIdx.y.
//   y=0: attention score s[b,t] = dot(targets@W_w^T + W_b, history)
//   y=1..3: g_x[y-1] = history @ {xu,xr,xg}_w^T + bias
// 512 threads, 4x8 register micro-tile, FFMA2 inner loop.
// ---------------------------------------------------------------------------
__global__ void proj_kernel(const float* __restrict__ targets,
                            const float* __restrict__ history,
                            const float* __restrict__ Ww,  const float* __restrict__ Wb,
                            const float* __restrict__ xuw, const float* __restrict__ xub,
                            const float* __restrict__ xrw, const float* __restrict__ xrb,
                            const float* __restrict__ xgw, const float* __restrict__ xgb)
{
    extern __shared__ float sm[];
    float* Hs  = sm;                 // [128 col/k][PJ row] history, transposed
    float* Ws  = Hs + 128 * PJ;      // [128 k][PJ o]       weight, transposed
    float* Ts  = Ws + 128 * PJ;      // [128 k][PJ row]     targets, transposed (y=0 only)
    float* bsm = Ts + 128 * PJ;      // [128] bias
    float* red = bsm + 128;          // [128 row][16] score reduction (y=0 only)

    const int tid = threadIdx.x;
    const int bt0 = blockIdx.x * 128;
    const int w   = blockIdx.y;

    const float* wsrc = (w == 0) ? Ww  : (w == 1) ? xuw : (w == 2) ? xrw : xgw;
    const float* bsrc = (w == 0) ? Wb  : (w == 1) ? xub : (w == 2) ? xrb : xgb;

    // Stage tiles (transposed: [k][row] / [k][o])
    for (int idx = tid; idx < 128 * 128; idx += 512) {
        int row = idx >> 7, k = idx & 127;
        Hs[k * PJ + row] = history[(size_t)(bt0 + row) * 128 + k];
        Ws[k * PJ + row] = wsrc[(size_t)row * 128 + k];   // row == o here
    }
    if (w == 0) {
        for (int idx = tid; idx < 128 * 128; idx += 512) {
            int row = idx >> 7, k = idx & 127;
            Ts[k * PJ + row] = targets[(size_t)(bt0 + row) * 128 + k];
        }
    }
    if (tid < 128) bsm[tid] = bsrc[tid];
    __syncthreads();

    const int tx = tid & 15, ty = tid >> 4;     // 16 x 32
    const int r0 = ty * 4, c0 = tx * 8;

    const float* A = (w == 0) ? Ts : Hs;

    u64 acc[4][4];
    #pragma unroll
    for (int i = 0; i < 4; i++)
        #pragma unroll
        for (int j = 0; j < 4; j++) acc[i][j] = 0ull;

    #pragma unroll 4
    for (int k = 0; k < 128; k++) {
        const float* Ak = A + k * PJ;
        const float* Wk = Ws + k * PJ;
        float4 a4 = *(const float4*)(Ak + r0);
        ulonglong2 w01 = *(const ulonglong2*)(Wk + c0);       // cols c0..c0+3
        ulonglong2 w23 = *(const ulonglong2*)(Wk + c0 + 4);   // cols c0+4..c0+7
        u64 ad0 = dup2(a4.x), ad1 = dup2(a4.y), ad2 = dup2(a4.z), ad3 = dup2(a4.w);
        acc[0][0] = ffma2(ad0, w01.x, acc[0][0]);
        acc[0][1] = ffma2(ad0, w01.y, acc[0][1]);
        acc[0][2] = ffma2(ad0, w23.x, acc[0][2]);
        acc[0][3] = ffma2(ad0, w23.y, acc[0][3]);
        acc[1][0] = ffma2(ad1, w01.x, acc[1][0]);
        acc[1][1] = ffma2(ad1, w01.y, acc[1][1]);
        acc[1][2] = ffma2(ad1, w23.x, acc[1][2]);
        acc[1][3] = ffma2(ad1, w23.y, acc[1][3]);
        acc[2][0] = ffma2(ad2, w01.x, acc[2][0]);
        acc[2][1] = ffma2(ad2, w01.y, acc[2][1]);
        acc[2][2] = ffma2(ad2, w23.x, acc[2][2]);
        acc[2][3] = ffma2(ad2, w23.y, acc[2][3]);
        acc[3][0] = ffma2(ad3, w01.x, acc[3][0]);
        acc[3][1] = ffma2(ad3, w01.y, acc[3][1]);
        acc[3][2] = ffma2(ad3, w23.x, acc[3][2]);
        acc[3][3] = ffma2(ad3, w23.y, acc[3][3]);
    }

    if (w == 0) {
        // score: per-row dot of (aw + bias) with history row
        #pragma unroll
        for (int i = 0; i < 4; i++) {
            float p = 0.0f;
            #pragma unroll
            for (int jj = 0; jj < 4; jj++) {
                float2 v = unpack2(acc[i][jj]);
                int c = c0 + jj * 2;
                p += (v.x + bsm[c])     * Hs[c * PJ + (r0 + i)];
                p += (v.y + bsm[c + 1]) * Hs[(c + 1) * PJ + (r0 + i)];
            }
            red[(r0 + i) * 16 + tx] = p;
        }
        __syncthreads();
        if (tid < 128) {
            float s = 0.0f;
            #pragma unroll
            for (int x = 0; x < 16; x++) s += red[tid * 16 + x];
            g_s[(size_t)bt0 + tid] = s;
        }
    } else {
        float* dst = g_x + (size_t)(w - 1) * BT * 128 + (size_t)bt0 * 128;
        ulonglong2 b01 = *(const ulonglong2*)(bsm + c0);
        ulonglong2 b23 = *(const ulonglong2*)(bsm + c0 + 4);
        #pragma unroll
        for (int i = 0; i < 4; i++) {
            ulonglong2 o0, o1;
            o0.x = fadd2(acc[i][0], b01.x);
            o0.y = fadd2(acc[i][1], b01.y);
            o1.x = fadd2(acc[i][2], b23.x);
            o1.y = fadd2(acc[i][3], b23.y);
            *(ulonglong2*)&dst[(size_t)(r0 + i) * 128 + c0]     = o0;
            *(ulonglong2*)&dst[(size_t)(r0 + i) * 128 + c0 + 4] = o1;
        }
    }
}

// ---------------------------------------------------------------------------
// Kernel B: softmax over T per batch row.
// ---------------------------------------------------------------------------
__global__ void softmax_kernel()
{
    __shared__ float red[256];
    const int b = blockIdx.x;
    const int tid = threadIdx.x;

    float v = (tid < Tk) ? g_s[(size_t)b * Tk + tid] : -1e30f;
    red[tid] = v;
    __syncthreads();
    for (int s = 128; s > 0; s >>= 1) {
        if (tid < s) red[tid] = fmaxf(red[tid], red[tid + s]);
        __syncthreads();
    }
    const float mx = red[0];
    __syncthreads();
    float e = (tid < Tk) ? expf(v - mx) : 0.0f;
    red[tid] = e;
    __syncthreads();
    for (int s = 128; s > 0; s >>= 1) {
        if (tid < s) red[tid] += red[tid + s];
        __syncthreads();
    }
    const float inv = 1.0f / red[0];
    if (tid < Tk) g_att[(size_t)b * Tk + tid] = e * inv;
}

// ---------------------------------------------------------------------------
// Kernel C: persistent GRU-style scan + final linear.
// 128 blocks x 8 batch rows, 384 threads. Thread tid -> (gate m = tid/128,
// output col oc = tid%128). FFMA2 matvec, 2 syncthreads per step.
// ---------------------------------------------------------------------------
__global__ void scan_kernel(const float* __restrict__ targets,
                            const float* __restrict__ huw, const float* __restrict__ hub,
                            const float* __restrict__ hrw, const float* __restrict__ hrb,
                            const float* __restrict__ hgw, const float* __restrict__ hgb,
                            const float* __restrict__ ln2w, const float* __restrict__ ln2b,
                            float* __restrict__ out)
{
    extern __shared__ float sm[];
    float* W_s = sm;                          // [3][128 o][WS_STRIDE k]
    float* bsm = W_s + 3 * 128 * WS_STRIDE;   // [3][128]
    float* h_s = bsm + 3 * 128;               // [8][128]
    float* r_s = h_s + 8 * 128;               // [8][128] reset gate / targets stage
    float* u_s = r_s + 8 * 128;               // [8][128] scaled update gate

    const int tid = threadIdx.x;
    const int b0 = blockIdx.x * 8;

    {
        const float* hw[3] = {huw, hrw, hgw};
        const float* hb[3] = {hub, hrb, hgb};
        for (int mm = 0; mm < 3; mm++) {
            for (int idx = tid; idx < 128 * 128; idx += 384) {
                int o = idx >> 7, k = idx & 127;
                W_s[(mm * 128 + o) * WS_STRIDE + k] = hw[mm][idx];
            }
            if (tid < 128) bsm[mm * 128 + tid] = hb[mm][tid];
        }
    }
    for (int idx = tid; idx < 8 * 128; idx += 384) h_s[idx] = 0.0f;
    __syncthreads();

    const int m  = tid >> 7;     // 0: update u, 1: reset r, 2: candidate g + h update
    const int oc = tid & 127;
    const float* wrow = &W_s[(m * 128 + oc) * WS_STRIDE];
    const float  bias = bsm[m * 128 + oc];
    const float* xbase = g_x + (size_t)m * BT * 128 + oc;

    for (int t = 0; t < Tk; t++) {
        // issue global loads early (latency hidden behind matvec)
        float xv[8], attv[8];
        #pragma unroll
        for (int i = 0; i < 8; i++)
            xv[i] = xbase[(size_t)((b0 + i) * Tk + t) * 128];
        if (m == 0) {
            #pragma unroll
            for (int i = 0; i < 8; i++) attv[i] = g_att[(size_t)(b0 + i) * Tk + t];
        }

        u64 aA[8], aB[8];
        #pragma unroll
        for (int i = 0; i < 8; i++) { aA[i] = 0ull; aB[i] = 0ull; }

        #pragma unroll 4
        for (int k = 0; k < 128; k += 4) {
            ulonglong2 w2 = *(const ulonglong2*)&wrow[k];
            #pragma unroll
            for (int i = 0; i < 8; i++) {
                ulonglong2 h2 = *(const ulonglong2*)&h_s[i * 128 + k];
                aA[i] = ffma2(w2.x, h2.x, aA[i]);
                aB[i] = ffma2(w2.y, h2.y, aB[i]);
            }
        }
        float acc[8];
        #pragma unroll
        for (int i = 0; i < 8; i++) {
            float2 s2 = unpack2(fadd2(aA[i], aB[i]));
            acc[i] = s2.x + s2.y;
        }

        if (m == 0) {
            #pragma unroll
            for (int i = 0; i < 8; i++)
                u_s[i * 128 + oc] = sigmoidf_(acc[i] + bias + xv[i]) * attv[i];
        } else if (m == 1) {
            #pragma unroll
            for (int i = 0; i < 8; i++)
                r_s[i * 128 + oc] = sigmoidf_(acc[i] + bias + xv[i]);
        }
        __syncthreads();                 // u_s, r_s ready; matvec reads of h done

        if (m == 2) {
            #pragma unroll
            for (int i = 0; i < 8; i++) {
                float z = acc[i] + bias;                    // h@hg^T + hg_b
                float g = tanhf(xv[i] + r_s[i * 128 + oc] * z);
                float h = h_s[i * 128 + oc];
                h_s[i * 128 + oc] = h + u_s[i * 128 + oc] * (g - h);
            }
        }
        __syncthreads();                 // h ready for next step
    }

    // ---- final: out = concat(h, targets[:,0]) @ ln2_w^T + ln2_b ----
    for (int idx = tid; idx < 8 * 128; idx += 384)
        r_s[idx] = targets[(size_t)((b0 + (idx >> 7)) * Tk) * 128 + (idx & 127)];
    float* lw = W_s;   // [256 k][LN_STRIDE] transposed
    for (int idx = tid; idx < 128 * 256; idx += 384) {
        int o = idx >> 8, k2 = idx & 255;             // ln2_w[o][k2]
        lw[k2 * LN_STRIDE + o] = ln2w[idx];
    }
    __syncthreads();

    if (tid < 128) {
        const int o = tid;
        float acc2[8];
        const float b2 = ln2b[o];
        #pragma unroll
        for (int i = 0; i < 8; i++) acc2[i] = b2;
        #pragma unroll 2
        for (int k = 0; k < 128; k++) {
            float wh = lw[k * LN_STRIDE + o];
            float wt = lw[(128 + k) * LN_STRIDE + o];
            #pragma unroll
            for (int i = 0; i < 8; i++)
                acc2[i] += h_s[i * 128 + k] * wh + r_s[i * 128 + k] * wt;
        }
        #pragma unroll
        for (int i = 0; i < 8; i++)
            out[(size_t)(b0 + i) * 128 + o] = acc2[i];
    }
}

// ---------------------------------------------------------------------------
extern "C" void kernel_launch(void* const* d_in, const int* in_sizes, int n_in,
                              void* d_out, int out_size)
{
    const float* targets = (const float*)d_in[0];
    const float* history = (const float*)d_in[1];
    const float* Ww  = (const float*)d_in[2];
    const float* Wb  = (const float*)d_in[3];
    const float* xuw = (const float*)d_in[4];
    const float* xub = (const float*)d_in[5];
    const float* huw = (const float*)d_in[6];
    const float* hub = (const float*)d_in[7];
    const float* xrw = (const float*)d_in[8];
    const float* xrb = (const float*)d_in[9];
    const float* hrw = (const float*)d_in[10];
    const float* hrb = (const float*)d_in[11];
    const float* xgw = (const float*)d_in[12];
    const float* xgb = (const float*)d_in[13];
    const float* hgw = (const float*)d_in[14];
    const float* hgb = (const float*)d_in[15];
    const float* ln2w = (const float*)d_in[16];
    const float* ln2b = (const float*)d_in[17];
    float* out = (float*)d_out;

    const size_t smA = (size_t)(3 * 128 * PJ + 128 + 128 * 16) * sizeof(float);
    const size_t smC = (size_t)(3 * 128 * WS_STRIDE + 3 * 128 + 3 * 8 * 128) * sizeof(float);

    cudaFuncSetAttribute(proj_kernel, cudaFuncAttributeMaxDynamicSharedMemorySize, (int)smA);
    cudaFuncSetAttribute(scan_kernel, cudaFuncAttributeMaxDynamicSharedMemorySize, (int)smC);

    proj_kernel<<<dim3(BT / 128, 4), 512, smA>>>(targets, history, Ww, Wb,
                                                 xuw, xub, xrw, xrb, xgw, xgb);
    softmax_kernel<<<Bk, 256>>>();
    scan_kernel<<<Bk / 8, 384, smC>>>(targets, huw, hub, hrw, hrb, hgw, hgb,
                                      ln2w, ln2b, out);
}